// round 11
// baseline (speedup 1.0000x reference)
#include <cuda_runtime.h>

#define NN 8192
#define DD 512
#define G  128          // k_main grid; <= SM count so all co-resident
#define TPB 512

// deterministic scratch
__device__ float g_b[DD];
__device__ float g_pm[G], g_pe[G];
__device__ float g_pp[G * DD];
__device__ float g_u[DD];
__device__ float g_v[DD];
// barrier state (replay-safe: count self-resets, gen monotonically increments)
__device__ unsigned g_cnt[4];
__device__ unsigned g_gen[4];

__device__ __forceinline__ void gridbar(int i) {
    __syncthreads();
    if (threadIdx.x == 0) {
        volatile unsigned* gen = &g_gen[i];
        unsigned g0 = *gen;
        __threadfence();
        unsigned my = atomicAdd(&g_cnt[i], 1u);
        if (my == G - 1) {
            g_cnt[i] = 0;
            __threadfence();
            *gen = g0 + 1;
        } else {
            while (*gen == g0) { }
        }
        __threadfence();
    }
    __syncthreads();
}

// K1: persistent. X loads issued FIRST (16 independent LDG.128 in flight),
// then P0 (b = W @ a2, warps 0-3, hidden under the X loads) -> gridbar ->
// P1 dots/partials -> bar -> P2a global S + u -> bar -> P2b v.
__global__ void __launch_bounds__(TPB, 1) k_main(
    const float4* __restrict__ X4, const float* __restrict__ W,
    const float* __restrict__ att)
{
    __shared__ float4 sb[128];             // 2 KB
    __shared__ float4 sm_p[16][128];       // 32 KB
    __shared__ float sm_m[16], sm_e[16], s_sc[16];
    __shared__ float spm[G], sesc[G];
    __shared__ float sred;
    __shared__ float su[DD];               // 2 KB
    __shared__ float4 sv16[16];

    int t = threadIdx.x, b = blockIdx.x;
    int w = t >> 5, l = t & 31;
    const float4* W4 = (const float4*)W;

    // ---------- issue all X loads for this thread's 4 rows (nothing depends
    // on them until after the gridbar; they hide P0 + barrier latency)
    float4 x[4][4];
    {
        size_t base = (size_t)(b * 64 + w * 4) * 128 + l;
#pragma unroll
        for (int i = 0; i < 4; i++)
#pragma unroll
            for (int q = 0; q < 4; q++)
                x[i][q] = X4[base + (size_t)i * 128 + 32 * q];
    }

    // ---------- P0: b[k] = sum_o W[k,o]*a2[o]; warps 0-3, k = b*4+w
    if (w < 4) {
        int k = b * 4 + w;
        const float4* a4 = (const float4*)(att + DD);
        float acc0 = 0.f;
#pragma unroll
        for (int q = 0; q < 4; q++) {
            float4 wv = W4[k * 128 + l + 32 * q];
            float4 av = a4[l + 32 * q];
            acc0 += wv.x * av.x + wv.y * av.y + wv.z * av.z + wv.w * av.w;
        }
#pragma unroll
        for (int o = 16; o > 0; o >>= 1) acc0 += __shfl_down_sync(~0u, acc0, o);
        if (l == 0) g_b[k] = acc0;
    }
    gridbar(0);

    // ---------- P1: dots + softmax partials (x[][] already in flight/landed)
    if (t < 128) sb[t] = ((const float4*)g_b)[t];
    __syncthreads();

    float d0 = 0.f, d1 = 0.f, d2 = 0.f, d3 = 0.f;
#pragma unroll
    for (int q = 0; q < 4; q++) {
        float4 bq = sb[l + 32 * q];
        d0 += x[0][q].x * bq.x + x[0][q].y * bq.y + x[0][q].z * bq.z + x[0][q].w * bq.w;
        d1 += x[1][q].x * bq.x + x[1][q].y * bq.y + x[1][q].z * bq.z + x[1][q].w * bq.w;
        d2 += x[2][q].x * bq.x + x[2][q].y * bq.y + x[2][q].z * bq.z + x[2][q].w * bq.w;
        d3 += x[3][q].x * bq.x + x[3][q].y * bq.y + x[3][q].z * bq.z + x[3][q].w * bq.w;
    }
#pragma unroll
    for (int o = 16; o > 0; o >>= 1) {     // 4 independent chains, overlapped
        d0 += __shfl_xor_sync(~0u, d0, o);
        d1 += __shfl_xor_sync(~0u, d1, o);
        d2 += __shfl_xor_sync(~0u, d2, o);
        d3 += __shfl_xor_sync(~0u, d3, o);
    }
    float m = fmaxf(fmaxf(d0, d1), fmaxf(d2, d3));
    float c0 = expf(d0 - m), c1 = expf(d1 - m), c2 = expf(d2 - m), c3 = expf(d3 - m);
    float e = (c0 + c1) + (c2 + c3);
#pragma unroll
    for (int q = 0; q < 4; q++) {
        float4 s;
        s.x = c0 * x[0][q].x + c1 * x[1][q].x + c2 * x[2][q].x + c3 * x[3][q].x;
        s.y = c0 * x[0][q].y + c1 * x[1][q].y + c2 * x[2][q].y + c3 * x[3][q].y;
        s.z = c0 * x[0][q].z + c1 * x[1][q].z + c2 * x[2][q].z + c3 * x[3][q].z;
        s.w = c0 * x[0][q].w + c1 * x[1][q].w + c2 * x[2][q].w + c3 * x[3][q].w;
        sm_p[w][l + 32 * q] = s;
    }
    if (l == 0) { sm_m[w] = m; sm_e[w] = e; }
    __syncthreads();

    // block combine: scales once (t<16), then 128 threads combine
    if (t < 16) {
        float mb = sm_m[0];
#pragma unroll
        for (int q = 1; q < 16; q++) mb = fmaxf(mb, sm_m[q]);
        s_sc[t] = expf(sm_m[t] - mb);
        if (t == 0) sred = mb;
    }
    __syncthreads();
    if (t < 128) {
        float4 s = make_float4(0.f, 0.f, 0.f, 0.f);
#pragma unroll
        for (int q = 0; q < 16; q++) {
            float sc = s_sc[q];
            float4 p = sm_p[q][t];
            s.x += sc * p.x; s.y += sc * p.y; s.z += sc * p.z; s.w += sc * p.w;
        }
        ((float4*)(g_pp + b * DD))[t] = s;
    }
    if (t == 0) {
        float eb = 0.f;
#pragma unroll
        for (int q = 0; q < 16; q++) eb += s_sc[q] * sm_e[q];
        g_pm[b] = sred;
        g_pe[b] = eb;
    }
    gridbar(1);

    // ---------- P2a: global max, S, u[k] for k = b*4+w (w<4), scaled 1/S
    if (t < G) spm[t] = g_pm[t];
    __syncthreads();
    if (w == 0) {
        float gm = -1e30f;
#pragma unroll
        for (int q = 0; q < 4; q++) gm = fmaxf(gm, spm[l + 32 * q]);
#pragma unroll
        for (int o = 16; o > 0; o >>= 1) gm = fmaxf(gm, __shfl_xor_sync(~0u, gm, o));
        if (l == 0) sred = gm;
    }
    __syncthreads();
    float gm = sred;
    if (t < G) sesc[t] = expf(spm[t] - gm);
    __syncthreads();
    if (w == 0) {
        float s = 0.f;
#pragma unroll
        for (int q = 0; q < 4; q++) { int p = l + 32 * q; s += sesc[p] * g_pe[p]; }
#pragma unroll
        for (int o = 16; o > 0; o >>= 1) s += __shfl_xor_sync(~0u, s, o);
        if (l == 0) sred = s;
    }
    __syncthreads();
    float inv = 1.f / sred;
    if (w < 4) {
        int k = b * 4 + w;
        float acc2 = 0.f;
#pragma unroll
        for (int q = 0; q < 4; q++) { int p = l + 32 * q; acc2 += sesc[p] * g_pp[p * DD + k]; }
#pragma unroll
        for (int o = 16; o > 0; o >>= 1) acc2 += __shfl_down_sync(~0u, acc2, o);
        if (l == 0) g_u[k] = acc2 * inv;
    }
    gridbar(2);

    // ---------- P2b: block b owns float4 output column b; thread t handles k=t.
    su[t] = g_u[t];
    __syncthreads();
    {
        float u = su[t];
        float4 wv = W4[(size_t)t * 128 + b];
        float4 part = make_float4(u * wv.x, u * wv.y, u * wv.z, u * wv.w);
#pragma unroll
        for (int o = 16; o > 0; o >>= 1) {
            part.x += __shfl_down_sync(~0u, part.x, o);
            part.y += __shfl_down_sync(~0u, part.y, o);
            part.z += __shfl_down_sync(~0u, part.z, o);
            part.w += __shfl_down_sync(~0u, part.w, o);
        }
        if (l == 0) sv16[w] = part;
    }
    __syncthreads();
    if (t < 16) {
        float4 p = sv16[t];
#pragma unroll
        for (int o = 8; o > 0; o >>= 1) {
            p.x += __shfl_down_sync(0xFFFFu, p.x, o);
            p.y += __shfl_down_sync(0xFFFFu, p.y, o);
            p.z += __shfl_down_sync(0xFFFFu, p.z, o);
            p.w += __shfl_down_sync(0xFFFFu, p.w, o);
        }
        if (t == 0) ((float4*)g_v)[b] = p;
    }
}

// K2: out[i,:] = v. 512 blocks x 256 threads, 8 fully-unrolled stores per
// thread (512*256*8 = 1,048,576 float4 exactly -> no bounds check).
__global__ void k_bcast(float4* __restrict__ out) {
    __shared__ float4 sv[128];
    int t = threadIdx.x;
    if (t < 128) sv[t] = ((const float4*)g_v)[t];
    __syncthreads();
    float4 val = sv[t & 127];
    size_t base = (size_t)blockIdx.x * (256 * 8) + t;
#pragma unroll
    for (int i = 0; i < 8; i++)
        out[base + (size_t)i * 256] = val;
}

extern "C" void kernel_launch(void* const* d_in, const int* in_sizes, int n_in,
                              void* d_out, int out_size) {
    const float* X   = (const float*)d_in[0];  // node_features  [8192, 512]
    const float* W   = (const float*)d_in[1];  // weight_matrix  [512, 512]
    const float* att = (const float*)d_in[2];  // attention_vector [1024, 1]
    float* out = (float*)d_out;                // [8192, 512] fp32

    k_main<<<G, TPB>>>((const float4*)X, W, att);
    k_bcast<<<512, 256>>>((float4*)out);
}

// round 12
// speedup vs baseline: 1.0140x; 1.0140x over previous
#include <cuda_runtime.h>
#include <cuda_device_runtime_api.h>

#define NN 8192
#define DD 512
#define G  128          // k_part/k_fin grid; <= SM count so all co-resident
#define TPB 512

// deterministic scratch
__device__ float g_b[DD];
__device__ float g_pm[G], g_pe[G];
__device__ float g_pp[G * DD];
__device__ float g_u[DD];
__device__ float g_v[DD];
// barrier state (replay-safe: count self-resets, gen monotonically increments)
__device__ unsigned g_cnt[4];
__device__ unsigned g_gen[4];

__device__ __forceinline__ void gridbar(int i) {
    __syncthreads();
    if (threadIdx.x == 0) {
        volatile unsigned* gen = &g_gen[i];
        unsigned g0 = *gen;
        __threadfence();
        unsigned my = atomicAdd(&g_cnt[i], 1u);
        if (my == G - 1) {
            g_cnt[i] = 0;
            __threadfence();
            *gen = g0 + 1;
        } else {
            while (*gen == g0) { }
        }
        __threadfence();
    }
    __syncthreads();
}

// N1: b[k] = sum_o W[k,o] * a2[o]. 128 blocks x 4 warps, warp-per-row.
// Triggers at start so k_part can launch and issue X loads underneath.
__global__ void k_b(const float* __restrict__ W, const float* __restrict__ att) {
    cudaTriggerProgrammaticLaunchCompletion();
    const float4* W4 = (const float4*)W;
    const float4* a4 = (const float4*)(att + DD);
    int warp = threadIdx.x >> 5, lane = threadIdx.x & 31;
    int k = blockIdx.x * 4 + warp;           // 0..511
    float4 w0 = W4[k * 128 + lane];
    float4 w1 = W4[k * 128 + lane + 32];
    float4 w2 = W4[k * 128 + lane + 64];
    float4 w3 = W4[k * 128 + lane + 96];
    float4 a0 = a4[lane], a1 = a4[lane + 32], a2v = a4[lane + 64], a3 = a4[lane + 96];
    float acc = (w0.x * a0.x + w0.y * a0.y + w0.z * a0.z + w0.w * a0.w)
              + (w1.x * a1.x + w1.y * a1.y + w1.z * a1.z + w1.w * a1.w)
              + (w2.x * a2v.x + w2.y * a2v.y + w2.z * a2v.z + w2.w * a2v.w)
              + (w3.x * a3.x + w3.y * a3.y + w3.z * a3.z + w3.w * a3.w);
#pragma unroll
    for (int o = 16; o > 0; o >>= 1) acc += __shfl_down_sync(~0u, acc, o);
    if (lane == 0) g_b[k] = acc;
}

// N2 (PDL secondary of k_b): P1. X loads issued BEFORE the dependency sync,
// so the 16 MB read overlaps k_b's execution.
__global__ void __launch_bounds__(TPB, 1) k_part(const float4* __restrict__ X4) {
    __shared__ float4 sb[128];             // 2 KB
    __shared__ float4 sm_p[16][128];       // 32 KB
    __shared__ float sm_m[16], sm_e[16], s_sc[16];
    __shared__ float sred;

    int t = threadIdx.x, b = blockIdx.x;
    int w = t >> 5, l = t & 31;

    // issue all 16 independent X loads (do not depend on k_b)
    float4 x[4][4];
    {
        size_t base = (size_t)(b * 64 + w * 4) * 128 + l;
#pragma unroll
        for (int i = 0; i < 4; i++)
#pragma unroll
            for (int q = 0; q < 4; q++)
                x[i][q] = X4[base + (size_t)i * 128 + 32 * q];
    }
    cudaTriggerProgrammaticLaunchCompletion();   // let k_fin launch
    cudaGridDependencySynchronize();             // wait for g_b

    if (t < 128) sb[t] = ((const float4*)g_b)[t];
    __syncthreads();

    float d0 = 0.f, d1 = 0.f, d2 = 0.f, d3 = 0.f;
#pragma unroll
    for (int q = 0; q < 4; q++) {
        float4 bq = sb[l + 32 * q];
        d0 += x[0][q].x * bq.x + x[0][q].y * bq.y + x[0][q].z * bq.z + x[0][q].w * bq.w;
        d1 += x[1][q].x * bq.x + x[1][q].y * bq.y + x[1][q].z * bq.z + x[1][q].w * bq.w;
        d2 += x[2][q].x * bq.x + x[2][q].y * bq.y + x[2][q].z * bq.z + x[2][q].w * bq.w;
        d3 += x[3][q].x * bq.x + x[3][q].y * bq.y + x[3][q].z * bq.z + x[3][q].w * bq.w;
    }
#pragma unroll
    for (int o = 16; o > 0; o >>= 1) {     // 4 independent chains, overlapped
        d0 += __shfl_xor_sync(~0u, d0, o);
        d1 += __shfl_xor_sync(~0u, d1, o);
        d2 += __shfl_xor_sync(~0u, d2, o);
        d3 += __shfl_xor_sync(~0u, d3, o);
    }
    float m = fmaxf(fmaxf(d0, d1), fmaxf(d2, d3));
    float c0 = expf(d0 - m), c1 = expf(d1 - m), c2 = expf(d2 - m), c3 = expf(d3 - m);
    float e = (c0 + c1) + (c2 + c3);
#pragma unroll
    for (int q = 0; q < 4; q++) {
        float4 s;
        s.x = c0 * x[0][q].x + c1 * x[1][q].x + c2 * x[2][q].x + c3 * x[3][q].x;
        s.y = c0 * x[0][q].y + c1 * x[1][q].y + c2 * x[2][q].y + c3 * x[3][q].y;
        s.z = c0 * x[0][q].z + c1 * x[1][q].z + c2 * x[2][q].z + c3 * x[3][q].z;
        s.w = c0 * x[0][q].w + c1 * x[1][q].w + c2 * x[2][q].w + c3 * x[3][q].w;
        sm_p[w][l + 32 * q] = s;
    }
    if (l == 0) { sm_m[w] = m; sm_e[w] = e; }
    __syncthreads();

    if (t < 16) {
        float mb = sm_m[0];
#pragma unroll
        for (int q = 1; q < 16; q++) mb = fmaxf(mb, sm_m[q]);
        s_sc[t] = expf(sm_m[t] - mb);
        if (t == 0) sred = mb;
    }
    __syncthreads();
    if (t < 128) {
        float4 s = make_float4(0.f, 0.f, 0.f, 0.f);
#pragma unroll
        for (int q = 0; q < 16; q++) {
            float sc = s_sc[q];
            float4 p = sm_p[q][t];
            s.x += sc * p.x; s.y += sc * p.y; s.z += sc * p.z; s.w += sc * p.w;
        }
        ((float4*)(g_pp + b * DD))[t] = s;
    }
    if (t == 0) {
        float eb = 0.f;
#pragma unroll
        for (int q = 0; q < 16; q++) eb += s_sc[q] * sm_e[q];
        g_pm[b] = sred;
        g_pe[b] = eb;
    }
}

// N3 (PDL secondary of k_part): P2a (global S, u) -> gridbar -> P2b (v).
// Prefetches its W column before the dependency sync.
__global__ void __launch_bounds__(TPB, 1) k_fin(const float* __restrict__ W) {
    __shared__ float spm[G], sesc[G];
    __shared__ float sred;
    __shared__ float su[DD];
    __shared__ float4 sv16[16];

    int t = threadIdx.x, b = blockIdx.x;
    int w = t >> 5, l = t & 31;
    const float4* W4 = (const float4*)W;

    float4 wv = W4[(size_t)t * 128 + b];         // prefetch (independent)
    cudaTriggerProgrammaticLaunchCompletion();   // let k_bcast launch
    cudaGridDependencySynchronize();             // wait for partials

    if (t < G) spm[t] = g_pm[t];
    __syncthreads();
    if (w == 0) {
        float gm = -1e30f;
#pragma unroll
        for (int q = 0; q < 4; q++) gm = fmaxf(gm, spm[l + 32 * q]);
#pragma unroll
        for (int o = 16; o > 0; o >>= 1) gm = fmaxf(gm, __shfl_xor_sync(~0u, gm, o));
        if (l == 0) sred = gm;
    }
    __syncthreads();
    float gm = sred;
    if (t < G) sesc[t] = expf(spm[t] - gm);
    __syncthreads();
    if (w == 0) {
        float s = 0.f;
#pragma unroll
        for (int q = 0; q < 4; q++) { int p = l + 32 * q; s += sesc[p] * g_pe[p]; }
#pragma unroll
        for (int o = 16; o > 0; o >>= 1) s += __shfl_xor_sync(~0u, s, o);
        if (l == 0) sred = s;
    }
    __syncthreads();
    float inv = 1.f / sred;
    if (w < 4) {
        int k = b * 4 + w;
        float acc2 = 0.f;
#pragma unroll
        for (int q = 0; q < 4; q++) { int p = l + 32 * q; acc2 += sesc[p] * g_pp[p * DD + k]; }
#pragma unroll
        for (int o = 16; o > 0; o >>= 1) acc2 += __shfl_down_sync(~0u, acc2, o);
        if (l == 0) g_u[k] = acc2 * inv;
    }
    gridbar(0);

    su[t] = g_u[t];
    __syncthreads();
    {
        float u = su[t];
        float4 part = make_float4(u * wv.x, u * wv.y, u * wv.z, u * wv.w);
#pragma unroll
        for (int o = 16; o > 0; o >>= 1) {
            part.x += __shfl_down_sync(~0u, part.x, o);
            part.y += __shfl_down_sync(~0u, part.y, o);
            part.z += __shfl_down_sync(~0u, part.z, o);
            part.w += __shfl_down_sync(~0u, part.w, o);
        }
        if (l == 0) sv16[w] = part;
    }
    __syncthreads();
    if (t < 16) {
        float4 p = sv16[t];
#pragma unroll
        for (int o = 8; o > 0; o >>= 1) {
            p.x += __shfl_down_sync(0xFFFFu, p.x, o);
            p.y += __shfl_down_sync(0xFFFFu, p.y, o);
            p.z += __shfl_down_sync(0xFFFFu, p.z, o);
            p.w += __shfl_down_sync(0xFFFFu, p.w, o);
        }
        if (t == 0) ((float4*)g_v)[b] = p;
    }
}

// N4 (PDL secondary of k_fin): out[i,:] = v. 512 blocks x 256 threads,
// 8 fully-unrolled stores per thread (512*256*8 = 1,048,576 float4 exactly).
__global__ void k_bcast(float4* __restrict__ out) {
    __shared__ float4 sv[128];
    cudaGridDependencySynchronize();             // wait for g_v
    int t = threadIdx.x;
    if (t < 128) sv[t] = ((const float4*)g_v)[t];
    __syncthreads();
    float4 val = sv[t & 127];
    size_t base = (size_t)blockIdx.x * (256 * 8) + t;
#pragma unroll
    for (int i = 0; i < 8; i++)
        out[base + (size_t)i * 256] = val;
}

extern "C" void kernel_launch(void* const* d_in, const int* in_sizes, int n_in,
                              void* d_out, int out_size) {
    const float* X   = (const float*)d_in[0];  // node_features  [8192, 512]
    const float* W   = (const float*)d_in[1];  // weight_matrix  [512, 512]
    const float* att = (const float*)d_in[2];  // attention_vector [1024, 1]
    float* out = (float*)d_out;                // [8192, 512] fp32

    k_b<<<128, 128>>>(W, att);

    cudaLaunchAttribute pa[1];
    pa[0].id = cudaLaunchAttributeProgrammaticStreamSerialization;
    pa[0].val.programmaticStreamSerializationAllowed = 1;

    cudaLaunchConfig_t c1 = {};
    c1.gridDim = dim3(G); c1.blockDim = dim3(TPB);
    c1.stream = 0; c1.attrs = pa; c1.numAttrs = 1;
    cudaLaunchKernelEx(&c1, k_part, (const float4*)X);

    cudaLaunchConfig_t c2 = {};
    c2.gridDim = dim3(G); c2.blockDim = dim3(TPB);
    c2.stream = 0; c2.attrs = pa; c2.numAttrs = 1;
    cudaLaunchKernelEx(&c2, k_fin, W);

    cudaLaunchConfig_t c3 = {};
    c3.gridDim = dim3(512); c3.blockDim = dim3(256);
    c3.stream = 0; c3.attrs = pa; c3.numAttrs = 1;
    cudaLaunchKernelEx(&c3, k_bcast, (float4*)out);
}